// round 7
// baseline (speedup 1.0000x reference)
#include <cuda_runtime.h>

// ---------------- problem constants ----------------
#define GXN  1280
#define GYN  948
#define NB   4
#define NM   262144
#define NOUT 320
#define NQX2 80             // GXN/16
#define NQY  237            // GYN/4

#define TWO_PI_D 6.28318530717958647692
#define PI_F     3.14159265358979f
#define BETA_F ((float)(3.14159265358979323846 * 4.41021541424))
#define KXC ((float)(1280.0 / TWO_PI_D))
#define KYC ((float)(948.0  / TWO_PI_D))

// ---------------- device scratch ----------------
__device__ float2 g_grid [NB * GXN * GYN];          // 38.8 MB gridded k-space
__device__ float2 g_F    [NB * 16 * NQX2 * GYN];    // 38.8 MB x-DFT-folded (16 residue planes)
__device__ float2 g_stage1[NB * NOUT * GYN];        // 9.7 MB after x-DFT
__device__ float2 g_foldy[NB * 4 * NOUT * NQY];     // 9.7 MB radix-4 y-folded stage1
__device__ float2 g_W1[NQX2 * 20];                  // stage1 twiddles [q'][t] (c-independent)
__device__ float2 g_W2r[4 * 80 * NQY];              // stage2 twiddles [r4][jc][q'] (scaled)

// e^{2*pi*i*c/16}, c = 0..15
__device__ __constant__ float2 c_e16[16] = {
    { 1.000000000f,  0.000000000f}, { 0.923879533f,  0.382683432f},
    { 0.707106781f,  0.707106781f}, { 0.382683432f,  0.923879533f},
    { 0.000000000f,  1.000000000f}, {-0.382683432f,  0.923879533f},
    {-0.707106781f,  0.707106781f}, {-0.923879533f,  0.382683432f},
    {-1.000000000f,  0.000000000f}, {-0.923879533f, -0.382683432f},
    {-0.707106781f, -0.707106781f}, {-0.382683432f, -0.923879533f},
    { 0.000000000f, -1.000000000f}, { 0.382683432f, -0.923879533f},
    { 0.707106781f, -0.707106781f}, { 0.923879533f, -0.382683432f}
};

// ---------------- Kaiser-Bessel i0 ----------------
__device__ __forceinline__ float i0f(float x) {
    if (x < 3.75f) {
        float t = x * (1.0f / 3.75f);
        t *= t;
        return 1.0f + t * (3.5156229f + t * (3.0899424f + t * (1.2067492f +
               t * (0.2659732f + t * (0.0360768f + t * 0.0045813f)))));
    } else {
        float inv = 3.75f / x;
        float p = 0.39894228f + inv * (0.01328592f + inv * (0.00225319f +
                  inv * (-0.00157565f + inv * (0.00916281f + inv * (-0.02057706f +
                  inv * (0.02635537f + inv * (-0.01647633f + inv * 0.00392377f)))))));
        return __expf(x) * rsqrtf(x) * p;
    }
}

__device__ __forceinline__ float deapod_inv(int i, float invN) {
    float u = (float)(i - 160) * invN;
    float t = 19.45f - 36.0f * u * u;
    float s = PI_F * sqrtf(t);
    float e = __expf(s);
    float sh = 0.5f * (e - 1.0f / e);
    return s / sh;
}

// ---------------- kernel 1: twiddle precompute ----------------
__global__ void __launch_bounds__(256) twiddle_kernel() {
    const int T1 = NQX2 * 20;        // 1600
    const int T2 = 4 * 80 * NQY;     // 75840
    int idx = blockIdx.x * 256 + threadIdx.x;
    if (idx < T1) {
        int q = idx / 20, t = idx - q * 20;
        int ph = ((t - 10) * q) % 80; if (ph < 0) ph += 80;
        float sn, cs;
        sincosf((float)(TWO_PI_D / 80.0) * (float)ph, &sn, &cs);
        g_W1[idx] = make_float2(cs, sn);
    } else if (idx < T1 + T2) {
        int i2 = idx - T1;
        int r4 = i2 / (80 * NQY);
        int rem = i2 - r4 * (80 * NQY);
        int j = rem / NQY, q = rem - j * NQY;
        int k = 4 * j + r4 - 160;
        int ph = (k * q) % GYN; if (ph < 0) ph += GYN;
        float sn, cs;
        sincosf((float)((TWO_PI_D / (double)GYN) * (double)ph), &sn, &cs);
        const float scale = (float)(1.0 / sqrt((double)GXN * (double)GYN));
        g_W2r[i2] = make_float2(cs * scale, sn * scale);
    }
}

// ---------------- kernel 2: zero the grid ----------------
__global__ void __launch_bounds__(256) zero_kernel() {
    float4* p = reinterpret_cast<float4*>(g_grid);
    int idx = blockIdx.x * 256 + threadIdx.x;
    p[idx] = make_float4(0.f, 0.f, 0.f, 0.f);
}

// ---------------- kernel 3: KB gridding (v4/v2 vector red atomics) ----------------
__global__ void __launch_bounds__(256) gridding_kernel(const float2* __restrict__ ksp,
                                                       const float*  __restrict__ traj,
                                                       const float*  __restrict__ dcomp) {
    int idx = blockIdx.x * 256 + threadIdx.x;
    int b = idx >> 18;
    int m = idx & (NM - 1);

    float2 kv = ksp[idx];
    float  dc = dcomp[idx];
    float  tx = traj[(size_t)b * 2 * NM + m];
    float  ty = traj[(size_t)b * 2 * NM + NM + m];

    float yre = kv.x * dc, yim = kv.y * dc;
    float gx = tx * KXC, gy = ty * KYC;

    int ix0 = (int)floorf(gx - 3.0f) + 1;
    int iy0 = (int)floorf(gy - 3.0f) + 1;

    float wx[6], wy[6];
    int   xi[6];
#pragma unroll
    for (int j = 0; j < 6; j++) {
        float dx = gx - (float)(ix0 + j);
        float t  = fmaxf(1.0f - dx * dx * (1.0f / 9.0f), 0.0f);
        wx[j] = i0f(BETA_F * sqrtf(t));
        int xm = ix0 + j;
        xm += (xm < 0) ? GXN : 0;
        xm -= (xm >= GXN) ? GXN : 0;
        xi[j] = xm * GYN;

        float dy = gy - (float)(iy0 + j);
        float u  = fmaxf(1.0f - dy * dy * (1.0f / 9.0f), 0.0f);
        wy[j] = i0f(BETA_F * sqrtf(u));
    }

    int iy0m = iy0 % GYN; if (iy0m < 0) iy0m += GYN;
    bool nowrap = (iy0m + 5 < GYN);

    float2* gb = g_grid + (size_t)b * GXN * GYN;

    if (nowrap) {
        bool even = ((iy0m & 1) == 0);
#pragma unroll
        for (int jx = 0; jx < 6; jx++) {
            float wr = wx[jx] * yre;
            float wi = wx[jx] * yim;
            float vr[6], vi[6];
#pragma unroll
            for (int jy = 0; jy < 6; jy++) { vr[jy] = wr * wy[jy]; vi[jy] = wi * wy[jy]; }
            float2* base = gb + xi[jx] + iy0m;
            if (even) {
                asm volatile("red.global.add.v4.f32 [%0], {%1,%2,%3,%4};"
                    :: "l"(__cvta_generic_to_global(base)),     "f"(vr[0]), "f"(vi[0]), "f"(vr[1]), "f"(vi[1]) : "memory");
                asm volatile("red.global.add.v4.f32 [%0], {%1,%2,%3,%4};"
                    :: "l"(__cvta_generic_to_global(base + 2)), "f"(vr[2]), "f"(vi[2]), "f"(vr[3]), "f"(vi[3]) : "memory");
                asm volatile("red.global.add.v4.f32 [%0], {%1,%2,%3,%4};"
                    :: "l"(__cvta_generic_to_global(base + 4)), "f"(vr[4]), "f"(vi[4]), "f"(vr[5]), "f"(vi[5]) : "memory");
            } else {
                asm volatile("red.global.add.v2.f32 [%0], {%1,%2};"
                    :: "l"(__cvta_generic_to_global(base)),     "f"(vr[0]), "f"(vi[0]) : "memory");
                asm volatile("red.global.add.v4.f32 [%0], {%1,%2,%3,%4};"
                    :: "l"(__cvta_generic_to_global(base + 1)), "f"(vr[1]), "f"(vi[1]), "f"(vr[2]), "f"(vi[2]) : "memory");
                asm volatile("red.global.add.v4.f32 [%0], {%1,%2,%3,%4};"
                    :: "l"(__cvta_generic_to_global(base + 3)), "f"(vr[3]), "f"(vi[3]), "f"(vr[4]), "f"(vi[4]) : "memory");
                asm volatile("red.global.add.v2.f32 [%0], {%1,%2};"
                    :: "l"(__cvta_generic_to_global(base + 5)), "f"(vr[5]), "f"(vi[5]) : "memory");
            }
        }
    } else {
        int yi[6];
#pragma unroll
        for (int j = 0; j < 6; j++) {
            int ym = iy0m + j;
            ym -= (ym >= GYN) ? GYN : 0;
            yi[j] = ym;
        }
#pragma unroll
        for (int jx = 0; jx < 6; jx++) {
            float wr = wx[jx] * yre;
            float wi = wx[jx] * yim;
#pragma unroll
            for (int jy = 0; jy < 6; jy++) {
                float vr = wr * wy[jy];
                float vi = wi * wy[jy];
                float2* p = gb + (xi[jx] + yi[jy]);
                asm volatile("red.global.add.v2.f32 [%0], {%1, %2};"
                             :: "l"(__cvta_generic_to_global(p)), "f"(vr), "f"(vi) : "memory");
            }
        }
    }
}

// ---------------- kernel 4: 16-point DFT fold along x (2x radix-4) + twist ----------------
// F[b][c][q'][y] = e^{2pi i c q'/1280} * sum_{m=0}^{15} e^{2pi i c m/16} G[b][q'+80m][y]
__global__ void __launch_bounds__(256) fold16_kernel() {
    int idx = blockIdx.x * 256 + threadIdx.x;      // NB*80*948 = 303,360 = 1185*256
    int b = idx / (NQX2 * GYN);
    int rem = idx - b * (NQX2 * GYN);
    int q = rem / GYN;
    int y = rem - q * GYN;

    const float2* gb = g_grid + (size_t)b * GXN * GYN + (size_t)q * GYN + y;
    float2 g[16];
#pragma unroll
    for (int m = 0; m < 16; m++) g[m] = gb[(size_t)m * NQX2 * GYN];

    // stage 1: radix-4 over p (m = j + 4p), A[r4*4+j]
    float2 A[16];
#pragma unroll
    for (int j = 0; j < 4; j++) {
        float2 i0 = g[j], i1 = g[j + 4], i2 = g[j + 8], i3 = g[j + 12];
        A[0 * 4 + j] = make_float2(i0.x + i1.x + i2.x + i3.x, i0.y + i1.y + i2.y + i3.y);
        A[1 * 4 + j] = make_float2(i0.x - i1.y - i2.x + i3.y, i0.y + i1.x - i2.y - i3.x);
        A[2 * 4 + j] = make_float2(i0.x - i1.x + i2.x - i3.x, i0.y - i1.y + i2.y - i3.y);
        A[3 * 4 + j] = make_float2(i0.x + i1.y - i2.x - i3.y, i0.y - i1.x - i2.y + i3.x);
    }

    // twist rotation base e^{2pi i q/1280}
    float sw, cw;
    sincosf((float)(TWO_PI_D / 1280.0) * (float)q, &sw, &cw);
    float twr = 1.0f, twi = 0.0f;

    float2* ob = g_F + (size_t)b * 16 * NQX2 * GYN + (size_t)q * GYN + y;
#pragma unroll
    for (int c = 0; c < 16; c++) {
        int r4 = c & 3;
        float2 a0 = A[r4 * 4 + 0], a1 = A[r4 * 4 + 1], a2 = A[r4 * 4 + 2], a3 = A[r4 * 4 + 3];
        float2 w1 = c_e16[c], w2 = c_e16[(2 * c) & 15], w3 = c_e16[(3 * c) & 15];
        float xr = a0.x, xi = a0.y;
        xr = fmaf(w1.x, a1.x, xr); xr = fmaf(-w1.y, a1.y, xr);
        xi = fmaf(w1.x, a1.y, xi); xi = fmaf( w1.y, a1.x, xi);
        xr = fmaf(w2.x, a2.x, xr); xr = fmaf(-w2.y, a2.y, xr);
        xi = fmaf(w2.x, a2.y, xi); xi = fmaf( w2.y, a2.x, xi);
        xr = fmaf(w3.x, a3.x, xr); xr = fmaf(-w3.y, a3.y, xr);
        xi = fmaf(w3.x, a3.y, xi); xi = fmaf( w3.y, a3.x, xi);
        float fr = twr * xr - twi * xi;
        float fi = twr * xi + twi * xr;
        ob[(size_t)c * NQX2 * GYN] = make_float2(fr, fi);
        float ntr = twr * cw - twi * sw;
        twi = twr * sw + twi * cw;
        twr = ntr;
    }
}

// ---------------- kernel 5: stage1 GEMM  C1[b][16t+c][y] = sum_q' W1[q'][t] * F[b][c][q'][y] ----------------
// M=20 (t), N=948 (64-tiles), K=80; W1 resident in smem for whole block.
__global__ void __launch_bounds__(256) gemm1_kernel() {
    int b  = blockIdx.z;
    int c  = blockIdx.y;
    int n0 = blockIdx.x * 64;

    __shared__ float2 sW[NQX2][20];   // 12.8 KB
    __shared__ float2 sB[16][64];     // 8 KB

    int tid = threadIdx.x;
    int tx = tid & 63, ty = tid >> 6;

    for (int lin = tid; lin < NQX2 * 20; lin += 256) {
        int q = lin / 20, t = lin - q * 20;
        sW[q][t] = g_W1[lin];
    }

    float2 acc[5];
#pragma unroll
    for (int i = 0; i < 5; i++) acc[i] = make_float2(0.f, 0.f);

    const float2* Fp = g_F + ((size_t)(b * 16 + c)) * NQX2 * GYN;

    for (int kk = 0; kk < NQX2; kk += 16) {
#pragma unroll
        for (int l = 0; l < 4; l++) {
            int lin = tid + l * 256;
            int nl = lin & 63, kl = lin >> 6;
            int n = n0 + nl;
            sB[kl][nl] = (n < GYN) ? Fp[(size_t)(kk + kl) * GYN + n] : make_float2(0.f, 0.f);
        }
        __syncthreads();
#pragma unroll
        for (int k2 = 0; k2 < 16; k2++) {
            float2 bb = sB[k2][tx];
#pragma unroll
            for (int i = 0; i < 5; i++) {
                float2 a = sW[kk + k2][ty * 5 + i];
                acc[i].x = fmaf(a.x, bb.x, acc[i].x);
                acc[i].x = fmaf(-a.y, bb.y, acc[i].x);
                acc[i].y = fmaf(a.x, bb.y, acc[i].y);
                acc[i].y = fmaf(a.y, bb.x, acc[i].y);
            }
        }
        __syncthreads();
    }

    int n = n0 + tx;
    if (n < GYN) {
#pragma unroll
        for (int i = 0; i < 5; i++) {
            int t = ty * 5 + i;
            int krow = 16 * t + c;
            g_stage1[((size_t)b * NOUT + krow) * GYN + n] = acc[i];
        }
    }
}

// ---------------- kernel 6: radix-4 fold along y ----------------
__global__ void __launch_bounds__(256) foldy_kernel() {
    int idx = blockIdx.x * 256 + threadIdx.x;
    if (idx >= NB * NOUT * NQY) return;
    int b = idx / (NOUT * NQY);
    int rem = idx - b * (NOUT * NQY);
    int k = rem / NQY;
    int q = rem - k * NQY;

    const float2* cb = g_stage1 + ((size_t)b * NOUT + k) * GYN + q;
    float2 g0 = cb[0];
    float2 g1 = cb[NQY];
    float2 g2 = cb[2 * NQY];
    float2 g3 = cb[3 * NQY];

    float2 s0 = make_float2(g0.x + g1.x + g2.x + g3.x, g0.y + g1.y + g2.y + g3.y);
    float2 s1 = make_float2(g0.x - g1.y - g2.x + g3.y, g0.y + g1.x - g2.y - g3.x);
    float2 s2 = make_float2(g0.x - g1.x + g2.x - g3.x, g0.y - g1.y + g2.y - g3.y);
    float2 s3 = make_float2(g0.x + g1.y - g2.x - g3.y, g0.y - g1.x - g2.y + g3.x);

    size_t plane = (size_t)NOUT * NQY;
    size_t base = ((size_t)b * 4) * plane + (size_t)k * NQY + q;
    g_foldy[base]             = s0;
    g_foldy[base + plane]     = s1;
    g_foldy[base + 2 * plane] = s2;
    g_foldy[base + 3 * plane] = s3;
}

// ---------------- kernel 7: stage2 GEMM + deapod + |.| ----------------
// M=320 (16-tiles), N=80, K=237
__global__ void __launch_bounds__(256) gemm2_kernel(float* __restrict__ out) {
    int b  = blockIdx.z;
    int r4 = blockIdx.y;
    int m0 = blockIdx.x * 16;

    __shared__ float2 sA[16][16];   // 2 KB
    __shared__ float2 sB[16][80];   // 10 KB

    int tid = threadIdx.x;
    int tx = tid & 15, ty = tid >> 4;

    float2 acc[5];
#pragma unroll
    for (int j = 0; j < 5; j++) acc[j] = make_float2(0.f, 0.f);

    const float2* A  = g_foldy + ((size_t)(b * 4 + r4)) * NOUT * NQY;
    const float2* Bw = g_W2r + r4 * 80 * NQY;

    for (int kk = 0; kk < NQY; kk += 16) {
        {
            int ml = tid >> 4, kl = tid & 15;
            int kq = kk + kl;
            sA[kl][ml] = (kq < NQY) ? A[(size_t)(m0 + ml) * NQY + kq] : make_float2(0.f, 0.f);
        }
#pragma unroll
        for (int l = 0; l < 5; l++) {
            int lin = tid + l * 256;
            int kl = lin & 15, nl = lin >> 4;
            int kq = kk + kl;
            sB[kl][nl] = (kq < NQY) ? Bw[nl * NQY + kq] : make_float2(0.f, 0.f);
        }
        __syncthreads();
#pragma unroll
        for (int k = 0; k < 16; k++) {
            float2 a = sA[k][ty];
#pragma unroll
            for (int j = 0; j < 5; j++) {
                float2 bb = sB[k][j * 16 + tx];
                acc[j].x = fmaf(a.x, bb.x, acc[j].x);
                acc[j].x = fmaf(-a.y, bb.y, acc[j].x);
                acc[j].y = fmaf(a.x, bb.y, acc[j].y);
                acc[j].y = fmaf(a.y, bb.x, acc[j].y);
            }
        }
        __syncthreads();
    }

    int krow = m0 + ty;
    float dxv = deapod_inv(krow, 1.0f / (float)GXN);
    float* ob = out + (size_t)b * NOUT * NOUT;
#pragma unroll
    for (int j = 0; j < 5; j++) {
        int c_idx = 4 * (j * 16 + tx) + r4;
        float dyv = deapod_inv(c_idx, 1.0f / (float)GYN);
        float mag = hypotf(acc[j].x, acc[j].y);
        ob[krow * NOUT + c_idx] = mag * dxv * dyv;
    }
}

// ---------------- launch ----------------
extern "C" void kernel_launch(void* const* d_in, const int* in_sizes, int n_in,
                              void* d_out, int out_size) {
    (void)in_sizes; (void)n_in; (void)out_size;
    const float2* ksp   = (const float2*)d_in[0];
    const float*  traj  = (const float*)d_in[1];
    const float*  dcomp = (const float*)d_in[2];
    float* out = (float*)d_out;

    twiddle_kernel<<<303, 256>>>();                                  // 77,440 entries
    zero_kernel<<<9480, 256>>>();
    gridding_kernel<<<(NB * NM) / 256, 256>>>(ksp, traj, dcomp);
    fold16_kernel<<<1185, 256>>>();                                  // 303,360 threads (FIXED)
    gemm1_kernel<<<dim3(15, 16, NB), 256>>>();
    foldy_kernel<<<(NB * NOUT * NQY + 255) / 256, 256>>>();
    gemm2_kernel<<<dim3(20, 4, NB), 256>>>(out);
}